// round 1
// baseline (speedup 1.0000x reference)
#include <cuda_runtime.h>
#include <math.h>

#define NN 50000
#define EE 800000
#define IN_DIMC 32
#define HIDC 64
#define HEADSC 4
#define HCC 256
#define OUT_DIMC 128
#define LN_EPSF 1e-5f
#define NEG_SLOPEF 0.2f

// ---------------- scratch (device globals; no allocation allowed) ----------------
__device__ float g_h0[NN * HIDC];      // input projection output
__device__ float g_feat[NN * HCC];     // per-layer linear features
__device__ float g_agg[NN * HCC];      // per-layer aggregation output
__device__ float g_asrc[NN * HEADSC];
__device__ float g_adst[NN * HEADSC];
__device__ int   g_deg[NN];
__device__ int   g_off[NN + 1];
__device__ int   g_cur[NN];
__device__ int   g_srclist[EE];

__device__ __forceinline__ float eluf(float x) { return x > 0.f ? x : expm1f(x); }
__device__ __forceinline__ float lrelu(float x) { return x > 0.f ? x : NEG_SLOPEF * x; }

// ---------------- graph build ----------------
__global__ void zero_deg_kernel() {
    int i = blockIdx.x * blockDim.x + threadIdx.x;
    if (i < NN) g_deg[i] = 0;
}

__global__ void count_deg_kernel(const int* __restrict__ dst, int E) {
    int i = blockIdx.x * blockDim.x + threadIdx.x;
    if (i < E) atomicAdd(&g_deg[dst[i]], 1);
}

__global__ void scan_deg_kernel() {
    __shared__ int s[1024];
    int t = threadIdx.x;
    const int per = (NN + 1023) / 1024;
    int start = t * per;
    int end = min(NN, start + per);
    int local = 0;
    for (int i = start; i < end; i++) local += g_deg[i];
    s[t] = local;
    __syncthreads();
    // Hillis-Steele inclusive scan
    for (int d = 1; d < 1024; d <<= 1) {
        int v = (t >= d) ? s[t - d] : 0;
        __syncthreads();
        s[t] += v;
        __syncthreads();
    }
    int run = (t > 0) ? s[t - 1] : 0;
    for (int i = start; i < end; i++) {
        g_off[i] = run;
        g_cur[i] = run;
        run += g_deg[i];
    }
    if (t == 1023) g_off[NN] = s[1023];
}

__global__ void scatter_kernel(const int* __restrict__ src, const int* __restrict__ dst, int E) {
    int i = blockIdx.x * blockDim.x + threadIdx.x;
    if (i < E) {
        int p = atomicAdd(&g_cur[dst[i]], 1);
        g_srclist[p] = src[i];
    }
}

// ---------------- tiled SGEMM: C[M,Ncol] = act(A[M,K] @ B[K,Ncol] + bias) ----------------
#define BM 64
#define BN 64
#define BK 16
__global__ void gemm_kernel(const float* __restrict__ A, const float* __restrict__ B,
                            const float* __restrict__ bias, float* __restrict__ C,
                            int M, int Ncol, int K, int act) {
    __shared__ float sA[BK][BM];
    __shared__ float sB[BK][BN];
    int tid = threadIdx.x;
    int bm = blockIdx.x * BM, bn = blockIdx.y * BN;
    int ty = tid / 16, tx = tid % 16;
    float acc[4][4] = {};
    int arow = tid >> 2;        // 0..63
    int akc  = (tid & 3) * 4;   // 0,4,8,12
    int brow = tid >> 4;        // 0..15
    int bcol = (tid & 15) * 4;  // 0..60

    for (int k0 = 0; k0 < K; k0 += BK) {
        float4 av = make_float4(0.f, 0.f, 0.f, 0.f);
        int gr = bm + arow;
        if (gr < M) av = *reinterpret_cast<const float4*>(A + (size_t)gr * K + k0 + akc);
        sA[akc + 0][arow] = av.x;
        sA[akc + 1][arow] = av.y;
        sA[akc + 2][arow] = av.z;
        sA[akc + 3][arow] = av.w;
        float4 bv = *reinterpret_cast<const float4*>(B + (size_t)(k0 + brow) * Ncol + bn + bcol);
        *reinterpret_cast<float4*>(&sB[brow][bcol]) = bv;
        __syncthreads();
#pragma unroll
        for (int k = 0; k < BK; k++) {
            float4 a4 = *reinterpret_cast<const float4*>(&sA[k][ty * 4]);
            float4 b4 = *reinterpret_cast<const float4*>(&sB[k][tx * 4]);
            float a[4] = {a4.x, a4.y, a4.z, a4.w};
            float b[4] = {b4.x, b4.y, b4.z, b4.w};
#pragma unroll
            for (int i = 0; i < 4; i++)
#pragma unroll
                for (int j = 0; j < 4; j++) acc[i][j] = fmaf(a[i], b[j], acc[i][j]);
        }
        __syncthreads();
    }
#pragma unroll
    for (int i = 0; i < 4; i++) {
        int r = bm + ty * 4 + i;
        if (r >= M) break;
#pragma unroll
        for (int j = 0; j < 4; j++) {
            int c = bn + tx * 4 + j;
            float v = acc[i][j];
            if (bias) v += bias[c];
            if (act) v = eluf(v);
            C[(size_t)r * Ncol + c] = v;
        }
    }
}

// ---------------- attention scores: per (node, head) dot products ----------------
__global__ void att_scores_kernel(const float* __restrict__ feat,
                                  const float* __restrict__ att_src,
                                  const float* __restrict__ att_dst) {
    int n = blockIdx.x;
    int t = threadIdx.x;  // 128
    int h = t >> 5, lane = t & 31;
    const float* f = feat + (size_t)n * HCC + h * HIDC;
    float s1 = f[lane] * att_src[h * HIDC + lane] + f[lane + 32] * att_src[h * HIDC + lane + 32];
    float s2 = f[lane] * att_dst[h * HIDC + lane] + f[lane + 32] * att_dst[h * HIDC + lane + 32];
#pragma unroll
    for (int o = 16; o; o >>= 1) {
        s1 += __shfl_xor_sync(0xffffffffu, s1, o);
        s2 += __shfl_xor_sync(0xffffffffu, s2, o);
    }
    if (lane == 0) {
        g_asrc[n * HEADSC + h] = s1;
        g_adst[n * HEADSC + h] = s2;
    }
}

// ---------------- GAT aggregation: segment softmax + weighted sum (self-loop implicit) ----------------
__global__ void gat_aggregate_kernel(const float* __restrict__ feat,
                                     const float* __restrict__ bias,
                                     float* __restrict__ out) {
    int d = blockIdx.x;
    int tid = threadIdx.x;  // 256
    __shared__ float s_m[HEADSC], s_den[HEADSC], s_adst[HEADSC];
    __shared__ float s_red[8 * HEADSC];
    __shared__ float s_alpha[64 * HEADSC];
    __shared__ int s_src[64];

    int base = g_off[d];
    int deg = g_off[d + 1] - base;
    if (tid < HEADSC) s_adst[tid] = g_adst[d * HEADSC + tid];
    __syncthreads();
    float adst[HEADSC];
#pragma unroll
    for (int h = 0; h < HEADSC; h++) adst[h] = s_adst[h];

    int lane = tid & 31, warp = tid >> 5;

    // ---- pass 1: per-head max ----
    float lmax[HEADSC];
#pragma unroll
    for (int h = 0; h < HEADSC; h++) lmax[h] = -3.4e38f;
    for (int j = tid; j < deg; j += 256) {
        int s = g_srclist[base + j];
#pragma unroll
        for (int h = 0; h < HEADSC; h++) {
            float e = lrelu(g_asrc[s * HEADSC + h] + adst[h]);
            lmax[h] = fmaxf(lmax[h], e);
        }
    }
    if (tid == 0) {  // self-loop
#pragma unroll
        for (int h = 0; h < HEADSC; h++) {
            float e = lrelu(g_asrc[d * HEADSC + h] + adst[h]);
            lmax[h] = fmaxf(lmax[h], e);
        }
    }
#pragma unroll
    for (int o = 16; o; o >>= 1)
#pragma unroll
        for (int h = 0; h < HEADSC; h++) lmax[h] = fmaxf(lmax[h], __shfl_xor_sync(0xffffffffu, lmax[h], o));
    if (lane == 0)
#pragma unroll
        for (int h = 0; h < HEADSC; h++) s_red[warp * HEADSC + h] = lmax[h];
    __syncthreads();
    if (tid < HEADSC) {
        float m = -3.4e38f;
#pragma unroll
        for (int w = 0; w < 8; w++) m = fmaxf(m, s_red[w * HEADSC + tid]);
        s_m[tid] = m;
    }
    __syncthreads();
    float m[HEADSC];
#pragma unroll
    for (int h = 0; h < HEADSC; h++) m[h] = s_m[h];

    // ---- pass 2: per-head exp-sum ----
    float lsum[HEADSC] = {0.f, 0.f, 0.f, 0.f};
    for (int j = tid; j < deg; j += 256) {
        int s = g_srclist[base + j];
#pragma unroll
        for (int h = 0; h < HEADSC; h++) {
            float e = lrelu(g_asrc[s * HEADSC + h] + adst[h]);
            lsum[h] += __expf(e - m[h]);
        }
    }
    if (tid == 0) {
#pragma unroll
        for (int h = 0; h < HEADSC; h++) {
            float e = lrelu(g_asrc[d * HEADSC + h] + adst[h]);
            lsum[h] += __expf(e - m[h]);
        }
    }
#pragma unroll
    for (int o = 16; o; o >>= 1)
#pragma unroll
        for (int h = 0; h < HEADSC; h++) lsum[h] += __shfl_xor_sync(0xffffffffu, lsum[h], o);
    if (lane == 0)
#pragma unroll
        for (int h = 0; h < HEADSC; h++) s_red[warp * HEADSC + h] = lsum[h];
    __syncthreads();
    if (tid < HEADSC) {
        float sm = 0.f;
#pragma unroll
        for (int w = 0; w < 8; w++) sm += s_red[w * HEADSC + tid];
        s_den[tid] = sm + 1e-16f;
    }
    __syncthreads();
    float den[HEADSC];
#pragma unroll
    for (int h = 0; h < HEADSC; h++) den[h] = s_den[h];

    // ---- pass 3: chunked weighted aggregation (total = deg real edges + 1 self-loop) ----
    int c = tid;
    int hc = c >> 6;
    float acc = 0.f;
    int total = deg + 1;
    for (int ch = 0; ch < total; ch += 64) {
        int eidx = ch + (tid >> 2);
        int h = tid & 3;
        if (eidx < total) {
            int s = (eidx < deg) ? g_srclist[base + eidx] : d;
            float e = lrelu(g_asrc[s * HEADSC + h] + adst[h]);
            s_alpha[(tid >> 2) * HEADSC + h] = __expf(e - m[h]) / den[h];
            if (h == 0) s_src[tid >> 2] = s;
        }
        __syncthreads();
        int lim = min(64, total - ch);
        for (int j = 0; j < lim; j++) {
            acc = fmaf(s_alpha[j * HEADSC + hc], feat[(size_t)s_src[j] * HCC + c], acc);
        }
        __syncthreads();
    }
    out[(size_t)d * HCC + c] = eluf(acc + bias[c]);
}

// ---------------- fused out projection + layernorm ----------------
__global__ void out_ln_kernel(const float* __restrict__ hin, const float* __restrict__ Wout,
                              const float* __restrict__ bout, const float* __restrict__ gamma,
                              const float* __restrict__ beta, float* __restrict__ out) {
    int n = blockIdx.x;
    int t = threadIdx.x;  // 128
    __shared__ float sh[HCC];
    __shared__ float red[128];
    sh[t] = hin[(size_t)n * HCC + t];
    sh[t + 128] = hin[(size_t)n * HCC + t + 128];
    __syncthreads();
    float acc = bout[t];
#pragma unroll 8
    for (int k = 0; k < HCC; k++) acc = fmaf(sh[k], Wout[k * OUT_DIMC + t], acc);
    // mean
    red[t] = acc;
    __syncthreads();
    for (int o = 64; o; o >>= 1) {
        if (t < o) red[t] += red[t + o];
        __syncthreads();
    }
    float mu = red[0] * (1.f / OUT_DIMC);
    __syncthreads();
    float dv = acc - mu;
    red[t] = dv * dv;
    __syncthreads();
    for (int o = 64; o; o >>= 1) {
        if (t < o) red[t] += red[t + o];
        __syncthreads();
    }
    float var = red[0] * (1.f / OUT_DIMC);
    float inv = rsqrtf(var + LN_EPSF);
    out[(size_t)n * OUT_DIMC + t] = dv * inv * gamma[t] + beta[t];
}

// ---------------- launch ----------------
extern "C" void kernel_launch(void* const* d_in, const int* in_sizes, int n_in,
                              void* d_out, int out_size) {
    const float* x     = (const float*)d_in[0];
    const int*   ei    = (const int*)d_in[1];
    const float* W_in  = (const float*)d_in[2];
    const float* b_in  = (const float*)d_in[3];
    const float* lin0  = (const float*)d_in[4];
    const float* att0s = (const float*)d_in[5];
    const float* att0d = (const float*)d_in[6];
    const float* bias0 = (const float*)d_in[7];
    const float* lin1  = (const float*)d_in[8];
    const float* att1s = (const float*)d_in[9];
    const float* att1d = (const float*)d_in[10];
    const float* bias1 = (const float*)d_in[11];
    const float* Wout  = (const float*)d_in[12];
    const float* bout  = (const float*)d_in[13];
    const float* gamma = (const float*)d_in[14];
    const float* beta  = (const float*)d_in[15];
    float* out = (float*)d_out;

    int E = in_sizes[1] / 2;
    if (E > EE) E = EE;
    const int* srcp = ei;
    const int* dstp = ei + E;

    float *h0p = nullptr, *featp = nullptr, *aggp = nullptr;
    cudaGetSymbolAddress((void**)&h0p, g_h0);
    cudaGetSymbolAddress((void**)&featp, g_feat);
    cudaGetSymbolAddress((void**)&aggp, g_agg);

    // graph build (CSR of incoming edges per dst)
    zero_deg_kernel<<<(NN + 255) / 256, 256>>>();
    count_deg_kernel<<<(E + 255) / 256, 256>>>(dstp, E);
    scan_deg_kernel<<<1, 1024>>>();
    scatter_kernel<<<(E + 255) / 256, 256>>>(srcp, dstp, E);

    const int gx = (NN + BM - 1) / BM;

    // input projection + ELU
    gemm_kernel<<<dim3(gx, HIDC / BN), 256>>>(x, W_in, b_in, h0p, NN, HIDC, IN_DIMC, 1);

    // GAT layer 0
    gemm_kernel<<<dim3(gx, HCC / BN), 256>>>(h0p, lin0, nullptr, featp, NN, HCC, HIDC, 0);
    att_scores_kernel<<<NN, 128>>>(featp, att0s, att0d);
    gat_aggregate_kernel<<<NN, 256>>>(featp, bias0, aggp);

    // GAT layer 1
    gemm_kernel<<<dim3(gx, HCC / BN), 256>>>(aggp, lin1, nullptr, featp, NN, HCC, HCC, 0);
    att_scores_kernel<<<NN, 128>>>(featp, att1s, att1d);
    gat_aggregate_kernel<<<NN, 256>>>(featp, bias1, aggp);

    // output projection + layernorm
    out_ln_kernel<<<NN, 128>>>(aggp, Wout, bout, gamma, beta, out);
}

// round 2
// speedup vs baseline: 1.2419x; 1.2419x over previous
#include <cuda_runtime.h>
#include <math.h>

#define NN 50000
#define EE 800000
#define IN_DIMC 32
#define HIDC 64
#define HEADSC 4
#define HCC 256
#define OUT_DIMC 128
#define LN_EPSF 1e-5f
#define NEG_SLOPEF 0.2f

// ---------------- scratch (device globals; no allocation allowed) ----------------
__device__ float g_h0[NN * HIDC];
__device__ float g_feat[NN * HCC];
__device__ float g_agg[NN * HCC];
__device__ float g_asrc[NN * HEADSC];
__device__ float g_adst[NN * HEADSC];
__device__ int   g_deg[NN];
__device__ int   g_off[NN + 1];
__device__ int   g_cur[NN];
__device__ int   g_srclist[EE];

__device__ __forceinline__ float eluf(float x) { return x > 0.f ? x : expm1f(x); }
__device__ __forceinline__ float lrelu(float x) { return x > 0.f ? x : NEG_SLOPEF * x; }

// packed fp32x2 helpers (sm_100+ FFMA2)
__device__ __forceinline__ void fma2(unsigned long long& d, unsigned long long a, unsigned long long b) {
    asm("fma.rn.f32x2 %0, %1, %2, %0;" : "+l"(d) : "l"(a), "l"(b));
}
__device__ __forceinline__ unsigned long long dupf(float a) {
    unsigned long long r;
    asm("mov.b64 %0, {%1, %1};" : "=l"(r) : "f"(a));
    return r;
}
__device__ __forceinline__ unsigned long long packf(float a, float b) {
    unsigned long long r;
    asm("mov.b64 %0, {%1, %2};" : "=l"(r) : "f"(a), "f"(b));
    return r;
}
__device__ __forceinline__ void unpackf(unsigned long long v, float& lo, float& hi) {
    asm("mov.b64 {%0, %1}, %2;" : "=f"(lo), "=f"(hi) : "l"(v));
}

// ---------------- graph build ----------------
__global__ void zero_deg_kernel() {
    int i = blockIdx.x * blockDim.x + threadIdx.x;
    if (i < NN) g_deg[i] = 0;
}

__global__ void count_deg_kernel(const int* __restrict__ dst, int E) {
    int i = blockIdx.x * blockDim.x + threadIdx.x;
    if (i < E) atomicAdd(&g_deg[dst[i]], 1);
}

__global__ void scan_deg_kernel() {
    __shared__ int s[1024];
    int t = threadIdx.x;
    const int per = (NN + 1023) / 1024;
    int start = t * per;
    int end = min(NN, start + per);
    int local = 0;
    for (int i = start; i < end; i++) local += g_deg[i];
    s[t] = local;
    __syncthreads();
    for (int d = 1; d < 1024; d <<= 1) {
        int v = (t >= d) ? s[t - d] : 0;
        __syncthreads();
        s[t] += v;
        __syncthreads();
    }
    int run = (t > 0) ? s[t - 1] : 0;
    for (int i = start; i < end; i++) {
        g_off[i] = run;
        g_cur[i] = run;
        run += g_deg[i];
    }
    if (t == 1023) g_off[NN] = s[1023];
}

__global__ void scatter_kernel(const int* __restrict__ src, const int* __restrict__ dst, int E) {
    int i = blockIdx.x * blockDim.x + threadIdx.x;
    if (i < E) {
        int p = atomicAdd(&g_cur[dst[i]], 1);
        g_srclist[p] = src[i];
    }
}

// ---------------- small SGEMM (used for input projection, N=64) ----------------
#define BM 64
#define BN 64
#define BK 16
__global__ void gemm_kernel(const float* __restrict__ A, const float* __restrict__ B,
                            const float* __restrict__ bias, float* __restrict__ C,
                            int M, int Ncol, int K, int act) {
    __shared__ float sA[BK][BM];
    __shared__ float sB[BK][BN];
    int tid = threadIdx.x;
    int bm = blockIdx.x * BM, bn = blockIdx.y * BN;
    int ty = tid / 16, tx = tid % 16;
    float acc[4][4] = {};
    int arow = tid >> 2;
    int akc  = (tid & 3) * 4;
    int brow = tid >> 4;
    int bcol = (tid & 15) * 4;

    for (int k0 = 0; k0 < K; k0 += BK) {
        float4 av = make_float4(0.f, 0.f, 0.f, 0.f);
        int gr = bm + arow;
        if (gr < M) av = *reinterpret_cast<const float4*>(A + (size_t)gr * K + k0 + akc);
        sA[akc + 0][arow] = av.x;
        sA[akc + 1][arow] = av.y;
        sA[akc + 2][arow] = av.z;
        sA[akc + 3][arow] = av.w;
        float4 bv = *reinterpret_cast<const float4*>(B + (size_t)(k0 + brow) * Ncol + bn + bcol);
        *reinterpret_cast<float4*>(&sB[brow][bcol]) = bv;
        __syncthreads();
#pragma unroll
        for (int k = 0; k < BK; k++) {
            float4 a4 = *reinterpret_cast<const float4*>(&sA[k][ty * 4]);
            float4 b4 = *reinterpret_cast<const float4*>(&sB[k][tx * 4]);
            float a[4] = {a4.x, a4.y, a4.z, a4.w};
            float b[4] = {b4.x, b4.y, b4.z, b4.w};
#pragma unroll
            for (int i = 0; i < 4; i++)
#pragma unroll
                for (int j = 0; j < 4; j++) acc[i][j] = fmaf(a[i], b[j], acc[i][j]);
        }
        __syncthreads();
    }
#pragma unroll
    for (int i = 0; i < 4; i++) {
        int r = bm + ty * 4 + i;
        if (r >= M) break;
#pragma unroll
        for (int j = 0; j < 4; j++) {
            int c = bn + tx * 4 + j;
            float v = acc[i][j];
            if (bias) v += bias[c];
            if (act) v = eluf(v);
            C[(size_t)r * Ncol + c] = v;
        }
    }
}

// ---------------- 128x128 SGEMM with f32x2 packed FMA ----------------
#define GBM 128
#define GBN 128
#define GBK 16
#define GAPAD 144  // 128 + 16: odd/even loader lanes hit disjoint banks

__global__ __launch_bounds__(256) void gemm128_kernel(
    const float* __restrict__ A, const float* __restrict__ B,
    float* __restrict__ C, int M, int Ncol, int K) {
    __shared__ float sA[GBK][GAPAD];
    __shared__ float sB[GBK][GBN];
    int tid = threadIdx.x;  // 256
    int bm = blockIdx.x * GBM, bn = blockIdx.y * GBN;
    int ty = tid >> 4, tx = tid & 15;

    int lrow = tid >> 1;         // 0..127  (A loader)
    int lkc  = (tid & 1) * 8;    // 0 or 8
    int lkb  = tid >> 4;         // 0..15   (B loader)
    int lcol = (tid & 15) * 8;   // 0..120

    unsigned long long acc[8][4];
#pragma unroll
    for (int i = 0; i < 8; i++)
#pragma unroll
        for (int j = 0; j < 4; j++) acc[i][j] = 0ull;

    for (int k0 = 0; k0 < K; k0 += GBK) {
        float4 av0 = make_float4(0.f, 0.f, 0.f, 0.f);
        float4 av1 = make_float4(0.f, 0.f, 0.f, 0.f);
        int gr = bm + lrow;
        if (gr < M) {
            av0 = *reinterpret_cast<const float4*>(A + (size_t)gr * K + k0 + lkc);
            av1 = *reinterpret_cast<const float4*>(A + (size_t)gr * K + k0 + lkc + 4);
        }
        sA[lkc + 0][lrow] = av0.x;
        sA[lkc + 1][lrow] = av0.y;
        sA[lkc + 2][lrow] = av0.z;
        sA[lkc + 3][lrow] = av0.w;
        sA[lkc + 4][lrow] = av1.x;
        sA[lkc + 5][lrow] = av1.y;
        sA[lkc + 6][lrow] = av1.z;
        sA[lkc + 7][lrow] = av1.w;
        float4 bv0 = *reinterpret_cast<const float4*>(B + (size_t)(k0 + lkb) * Ncol + bn + lcol);
        float4 bv1 = *reinterpret_cast<const float4*>(B + (size_t)(k0 + lkb) * Ncol + bn + lcol + 4);
        *reinterpret_cast<float4*>(&sB[lkb][lcol]) = bv0;
        *reinterpret_cast<float4*>(&sB[lkb][lcol + 4]) = bv1;
        __syncthreads();
#pragma unroll
        for (int k = 0; k < GBK; k++) {
            float4 a0 = *reinterpret_cast<const float4*>(&sA[k][ty * 4]);
            float4 a1 = *reinterpret_cast<const float4*>(&sA[k][64 + ty * 4]);
            float4 b0 = *reinterpret_cast<const float4*>(&sB[k][tx * 4]);
            float4 b1 = *reinterpret_cast<const float4*>(&sB[k][64 + tx * 4]);
            unsigned long long bp[4];
            bp[0] = packf(b0.x, b0.y);
            bp[1] = packf(b0.z, b0.w);
            bp[2] = packf(b1.x, b1.y);
            bp[3] = packf(b1.z, b1.w);
            float a[8] = {a0.x, a0.y, a0.z, a0.w, a1.x, a1.y, a1.z, a1.w};
#pragma unroll
            for (int i = 0; i < 8; i++) {
                unsigned long long ad = dupf(a[i]);
#pragma unroll
                for (int jp = 0; jp < 4; jp++) fma2(acc[i][jp], ad, bp[jp]);
            }
        }
        __syncthreads();
    }

#pragma unroll
    for (int i = 0; i < 8; i++) {
        int r = bm + ((i < 4) ? (ty * 4 + i) : (64 + ty * 4 + i - 4));
        if (r >= M) continue;
        float v[8];
#pragma unroll
        for (int jp = 0; jp < 4; jp++) unpackf(acc[i][jp], v[jp * 2], v[jp * 2 + 1]);
        float* crow = C + (size_t)r * Ncol + bn;
        *reinterpret_cast<float4*>(crow + tx * 4) = make_float4(v[0], v[1], v[2], v[3]);
        *reinterpret_cast<float4*>(crow + 64 + tx * 4) = make_float4(v[4], v[5], v[6], v[7]);
    }
}

// ---------------- attention scores ----------------
__global__ void att_scores_kernel(const float* __restrict__ feat,
                                  const float* __restrict__ att_src,
                                  const float* __restrict__ att_dst) {
    int n = blockIdx.x;
    int t = threadIdx.x;  // 128
    int h = t >> 5, lane = t & 31;
    const float* f = feat + (size_t)n * HCC + h * HIDC;
    float s1 = f[lane] * att_src[h * HIDC + lane] + f[lane + 32] * att_src[h * HIDC + lane + 32];
    float s2 = f[lane] * att_dst[h * HIDC + lane] + f[lane + 32] * att_dst[h * HIDC + lane + 32];
#pragma unroll
    for (int o = 16; o; o >>= 1) {
        s1 += __shfl_xor_sync(0xffffffffu, s1, o);
        s2 += __shfl_xor_sync(0xffffffffu, s2, o);
    }
    if (lane == 0) {
        g_asrc[n * HEADSC + h] = s1;
        g_adst[n * HEADSC + h] = s2;
    }
}

// ---------------- GAT aggregation ----------------
__global__ void gat_aggregate_kernel(const float* __restrict__ feat,
                                     const float* __restrict__ bias,
                                     float* __restrict__ out) {
    int d = blockIdx.x;
    int tid = threadIdx.x;  // 256
    __shared__ float s_m[HEADSC], s_den[HEADSC], s_adst[HEADSC];
    __shared__ float s_red[8 * HEADSC];
    __shared__ float s_alpha[64 * HEADSC];
    __shared__ int s_src[64];

    int base = g_off[d];
    int deg = g_off[d + 1] - base;
    if (tid < HEADSC) s_adst[tid] = g_adst[d * HEADSC + tid];
    __syncthreads();
    float adst[HEADSC];
#pragma unroll
    for (int h = 0; h < HEADSC; h++) adst[h] = s_adst[h];

    int lane = tid & 31, warp = tid >> 5;

    float lmax[HEADSC];
#pragma unroll
    for (int h = 0; h < HEADSC; h++) lmax[h] = -3.4e38f;
    for (int j = tid; j < deg; j += 256) {
        int s = g_srclist[base + j];
#pragma unroll
        for (int h = 0; h < HEADSC; h++) {
            float e = lrelu(g_asrc[s * HEADSC + h] + adst[h]);
            lmax[h] = fmaxf(lmax[h], e);
        }
    }
    if (tid == 0) {
#pragma unroll
        for (int h = 0; h < HEADSC; h++) {
            float e = lrelu(g_asrc[d * HEADSC + h] + adst[h]);
            lmax[h] = fmaxf(lmax[h], e);
        }
    }
#pragma unroll
    for (int o = 16; o; o >>= 1)
#pragma unroll
        for (int h = 0; h < HEADSC; h++) lmax[h] = fmaxf(lmax[h], __shfl_xor_sync(0xffffffffu, lmax[h], o));
    if (lane == 0)
#pragma unroll
        for (int h = 0; h < HEADSC; h++) s_red[warp * HEADSC + h] = lmax[h];
    __syncthreads();
    if (tid < HEADSC) {
        float m = -3.4e38f;
#pragma unroll
        for (int w = 0; w < 8; w++) m = fmaxf(m, s_red[w * HEADSC + tid]);
        s_m[tid] = m;
    }
    __syncthreads();
    float m[HEADSC];
#pragma unroll
    for (int h = 0; h < HEADSC; h++) m[h] = s_m[h];

    float lsum[HEADSC] = {0.f, 0.f, 0.f, 0.f};
    for (int j = tid; j < deg; j += 256) {
        int s = g_srclist[base + j];
#pragma unroll
        for (int h = 0; h < HEADSC; h++) {
            float e = lrelu(g_asrc[s * HEADSC + h] + adst[h]);
            lsum[h] += __expf(e - m[h]);
        }
    }
    if (tid == 0) {
#pragma unroll
        for (int h = 0; h < HEADSC; h++) {
            float e = lrelu(g_asrc[d * HEADSC + h] + adst[h]);
            lsum[h] += __expf(e - m[h]);
        }
    }
#pragma unroll
    for (int o = 16; o; o >>= 1)
#pragma unroll
        for (int h = 0; h < HEADSC; h++) lsum[h] += __shfl_xor_sync(0xffffffffu, lsum[h], o);
    if (lane == 0)
#pragma unroll
        for (int h = 0; h < HEADSC; h++) s_red[warp * HEADSC + h] = lsum[h];
    __syncthreads();
    if (tid < HEADSC) {
        float sm = 0.f;
#pragma unroll
        for (int w = 0; w < 8; w++) sm += s_red[w * HEADSC + tid];
        s_den[tid] = sm + 1e-16f;
    }
    __syncthreads();
    float den[HEADSC];
#pragma unroll
    for (int h = 0; h < HEADSC; h++) den[h] = s_den[h];

    int c = tid;
    int hc = c >> 6;
    float acc = 0.f;
    int total = deg + 1;
    for (int ch = 0; ch < total; ch += 64) {
        int eidx = ch + (tid >> 2);
        int h = tid & 3;
        if (eidx < total) {
            int s = (eidx < deg) ? g_srclist[base + eidx] : d;
            float e = lrelu(g_asrc[s * HEADSC + h] + adst[h]);
            s_alpha[(tid >> 2) * HEADSC + h] = __expf(e - m[h]) / den[h];
            if (h == 0) s_src[tid >> 2] = s;
        }
        __syncthreads();
        int lim = min(64, total - ch);
        for (int j = 0; j < lim; j++) {
            acc = fmaf(s_alpha[j * HEADSC + hc], feat[(size_t)s_src[j] * HCC + c], acc);
        }
        __syncthreads();
    }
    out[(size_t)d * HCC + c] = eluf(acc + bias[c]);
}

// ---------------- fused out projection + layernorm (32 nodes / block, f32x2) ----------------
#define ONB 32  // nodes per block
__global__ __launch_bounds__(256) void onl_kernel(
    const float* __restrict__ hin, const float* __restrict__ Wout,
    const float* __restrict__ bout, const float* __restrict__ gamma,
    const float* __restrict__ beta, float* __restrict__ out) {
    __shared__ float sA[32][ONB + 1];      // [k][node]
    __shared__ float sB[32][OUT_DIMC];     // [k][col]
    int tid = threadIdx.x;                 // 256
    int bm = blockIdx.x * ONB;
    int ty = tid >> 5;                     // 0..7 -> node group
    int tx = tid & 31;                     // lane -> col group (tx*4 .. +3)

    int lrow = tid >> 3;                   // 0..31 (A loader: node)
    int lkc  = (tid & 7) * 4;              // 0..28 (A loader: k chunk)
    int lkb  = tid >> 3;                   // 0..31 (B loader: k row)
    int lc16 = (tid & 7) * 16;             // 0..112 (B loader: col chunk of 16)

    unsigned long long acc[4][2];
#pragma unroll
    for (int i = 0; i < 4; i++) { acc[i][0] = 0ull; acc[i][1] = 0ull; }

    for (int k0 = 0; k0 < HCC; k0 += 32) {
        float4 av = make_float4(0.f, 0.f, 0.f, 0.f);
        int gr = bm + lrow;
        if (gr < NN) av = *reinterpret_cast<const float4*>(hin + (size_t)gr * HCC + k0 + lkc);
        sA[lkc + 0][lrow] = av.x;
        sA[lkc + 1][lrow] = av.y;
        sA[lkc + 2][lrow] = av.z;
        sA[lkc + 3][lrow] = av.w;
#pragma unroll
        for (int q = 0; q < 4; q++) {
            float4 bv = *reinterpret_cast<const float4*>(Wout + (size_t)(k0 + lkb) * OUT_DIMC + lc16 + q * 4);
            *reinterpret_cast<float4*>(&sB[lkb][lc16 + q * 4]) = bv;
        }
        __syncthreads();
#pragma unroll 8
        for (int k = 0; k < 32; k++) {
            float4 b4 = *reinterpret_cast<const float4*>(&sB[k][tx * 4]);
            unsigned long long bp0 = packf(b4.x, b4.y);
            unsigned long long bp1 = packf(b4.z, b4.w);
#pragma unroll
            for (int i = 0; i < 4; i++) {
                unsigned long long ad = dupf(sA[k][ty * 4 + i]);
                fma2(acc[i][0], ad, bp0);
                fma2(acc[i][1], ad, bp1);
            }
        }
        __syncthreads();
    }

    // epilogue: bias + layernorm; each output row lives entirely in one warp
    float b0 = bout[tx * 4 + 0], b1 = bout[tx * 4 + 1], b2 = bout[tx * 4 + 2], b3 = bout[tx * 4 + 3];
    float g0 = gamma[tx * 4 + 0], g1 = gamma[tx * 4 + 1], g2 = gamma[tx * 4 + 2], g3 = gamma[tx * 4 + 3];
    float be0 = beta[tx * 4 + 0], be1 = beta[tx * 4 + 1], be2 = beta[tx * 4 + 2], be3 = beta[tx * 4 + 3];
#pragma unroll
    for (int i = 0; i < 4; i++) {
        int r = bm + ty * 4 + i;
        float v[4];
        unpackf(acc[i][0], v[0], v[1]);
        unpackf(acc[i][1], v[2], v[3]);
        v[0] += b0; v[1] += b1; v[2] += b2; v[3] += b3;
        float psum = v[0] + v[1] + v[2] + v[3];
#pragma unroll
        for (int o = 16; o; o >>= 1) psum += __shfl_xor_sync(0xffffffffu, psum, o);
        float mu = psum * (1.f / OUT_DIMC);
        float d0 = v[0] - mu, d1 = v[1] - mu, d2 = v[2] - mu, d3 = v[3] - mu;
        float pss = d0 * d0 + d1 * d1 + d2 * d2 + d3 * d3;
#pragma unroll
        for (int o = 16; o; o >>= 1) pss += __shfl_xor_sync(0xffffffffu, pss, o);
        float inv = rsqrtf(pss * (1.f / OUT_DIMC) + LN_EPSF);
        if (r < NN) {
            float4 res = make_float4(d0 * inv * g0 + be0, d1 * inv * g1 + be1,
                                     d2 * inv * g2 + be2, d3 * inv * g3 + be3);
            *reinterpret_cast<float4*>(out + (size_t)r * OUT_DIMC + tx * 4) = res;
        }
    }
}

// ---------------- launch ----------------
extern "C" void kernel_launch(void* const* d_in, const int* in_sizes, int n_in,
                              void* d_out, int out_size) {
    const float* x     = (const float*)d_in[0];
    const int*   ei    = (const int*)d_in[1];
    const float* W_in  = (const float*)d_in[2];
    const float* b_in  = (const float*)d_in[3];
    const float* lin0  = (const float*)d_in[4];
    const float* att0s = (const float*)d_in[5];
    const float* att0d = (const float*)d_in[6];
    const float* bias0 = (const float*)d_in[7];
    const float* lin1  = (const float*)d_in[8];
    const float* att1s = (const float*)d_in[9];
    const float* att1d = (const float*)d_in[10];
    const float* bias1 = (const float*)d_in[11];
    const float* Wout  = (const float*)d_in[12];
    const float* bout  = (const float*)d_in[13];
    const float* gamma = (const float*)d_in[14];
    const float* beta  = (const float*)d_in[15];
    float* out = (float*)d_out;

    int E = in_sizes[1] / 2;
    if (E > EE) E = EE;
    const int* srcp = ei;
    const int* dstp = ei + E;

    float *h0p = nullptr, *featp = nullptr, *aggp = nullptr;
    cudaGetSymbolAddress((void**)&h0p, g_h0);
    cudaGetSymbolAddress((void**)&featp, g_feat);
    cudaGetSymbolAddress((void**)&aggp, g_agg);

    // graph build (CSR of incoming edges per dst)
    zero_deg_kernel<<<(NN + 255) / 256, 256>>>();
    count_deg_kernel<<<(E + 255) / 256, 256>>>(dstp, E);
    scan_deg_kernel<<<1, 1024>>>();
    scatter_kernel<<<(E + 255) / 256, 256>>>(srcp, dstp, E);

    // input projection + ELU  (N=64, small)
    gemm_kernel<<<dim3((NN + BM - 1) / BM, HIDC / BN), 256>>>(x, W_in, b_in, h0p, NN, HIDC, IN_DIMC, 1);

    const int gx128 = (NN + GBM - 1) / GBM;

    // GAT layer 0
    gemm128_kernel<<<dim3(gx128, HCC / GBN), 256>>>(h0p, lin0, featp, NN, HCC, HIDC);
    att_scores_kernel<<<NN, 128>>>(featp, att0s, att0d);
    gat_aggregate_kernel<<<NN, 256>>>(featp, bias0, aggp);

    // GAT layer 1
    gemm128_kernel<<<dim3(gx128, HCC / GBN), 256>>>(aggp, lin1, featp, NN, HCC, HCC);
    att_scores_kernel<<<NN, 128>>>(featp, att1s, att1d);
    gat_aggregate_kernel<<<NN, 256>>>(featp, bias1, aggp);

    // output projection + layernorm (fused, 32 nodes/block)
    onl_kernel<<<(NN + ONB - 1) / ONB, 256>>>(aggp, Wout, bout, gamma, beta, out);
}

// round 3
// speedup vs baseline: 1.7742x; 1.4286x over previous
#include <cuda_runtime.h>
#include <math.h>

#define NN 50000
#define EE 800000
#define IN_DIMC 32
#define HIDC 64
#define HEADSC 4
#define HCC 256
#define OUT_DIMC 128
#define LN_EPSF 1e-5f
#define NEG_SLOPEF 0.2f

// ---------------- scratch (device globals; no allocation allowed) ----------------
__device__ float g_h0[NN * HIDC];
__device__ float g_feat[NN * HCC];
__device__ float g_agg[NN * HCC];
__device__ float g_asrc[NN * HEADSC];
__device__ float g_adst[NN * HEADSC];
__device__ int   g_deg[NN];
__device__ int   g_off[NN + 1];
__device__ int   g_cur[NN];
__device__ int   g_srclist[EE];

__device__ __forceinline__ float eluf(float x) { return x > 0.f ? x : expm1f(x); }
__device__ __forceinline__ float lrelu(float x) { return x > 0.f ? x : NEG_SLOPEF * x; }

// packed fp32x2 helpers (sm_100+ FFMA2)
__device__ __forceinline__ void fma2(unsigned long long& d, unsigned long long a, unsigned long long b) {
    asm("fma.rn.f32x2 %0, %1, %2, %0;" : "+l"(d) : "l"(a), "l"(b));
}
__device__ __forceinline__ unsigned long long dupf(float a) {
    unsigned long long r;
    asm("mov.b64 %0, {%1, %1};" : "=l"(r) : "f"(a));
    return r;
}
__device__ __forceinline__ unsigned long long packf(float a, float b) {
    unsigned long long r;
    asm("mov.b64 %0, {%1, %2};" : "=l"(r) : "f"(a), "f"(b));
    return r;
}
__device__ __forceinline__ void unpackf(unsigned long long v, float& lo, float& hi) {
    asm("mov.b64 {%0, %1}, %2;" : "=f"(lo), "=f"(hi) : "l"(v));
}

// ---------------- graph build ----------------
__global__ void zero_deg_kernel() {
    int i = blockIdx.x * blockDim.x + threadIdx.x;
    if (i < NN) g_deg[i] = 0;
}

__global__ void count_deg_kernel(const int* __restrict__ dst, int E) {
    int i = blockIdx.x * blockDim.x + threadIdx.x;
    if (i < E) atomicAdd(&g_deg[dst[i]], 1);
}

__global__ void scan_deg_kernel() {
    __shared__ int s[1024];
    int t = threadIdx.x;
    const int per = (NN + 1023) / 1024;
    int start = t * per;
    int end = min(NN, start + per);
    int local = 0;
    for (int i = start; i < end; i++) local += g_deg[i];
    s[t] = local;
    __syncthreads();
    for (int d = 1; d < 1024; d <<= 1) {
        int v = (t >= d) ? s[t - d] : 0;
        __syncthreads();
        s[t] += v;
        __syncthreads();
    }
    int run = (t > 0) ? s[t - 1] : 0;
    for (int i = start; i < end; i++) {
        g_off[i] = run;
        g_cur[i] = run;
        run += g_deg[i];
    }
    if (t == 1023) g_off[NN] = s[1023];
}

__global__ void scatter_kernel(const int* __restrict__ src, const int* __restrict__ dst, int E) {
    int i = blockIdx.x * blockDim.x + threadIdx.x;
    if (i < E) {
        int p = atomicAdd(&g_cur[dst[i]], 1);
        g_srclist[p] = src[i];
    }
}

// ---------------- small SGEMM (input projection, N=64) ----------------
#define BM 64
#define BN 64
#define BK 16
__global__ void gemm_kernel(const float* __restrict__ A, const float* __restrict__ B,
                            const float* __restrict__ bias, float* __restrict__ C,
                            int M, int Ncol, int K, int act) {
    __shared__ float sA[BK][BM];
    __shared__ float sB[BK][BN];
    int tid = threadIdx.x;
    int bm = blockIdx.x * BM, bn = blockIdx.y * BN;
    int ty = tid / 16, tx = tid % 16;
    float acc[4][4] = {};
    int arow = tid >> 2;
    int akc  = (tid & 3) * 4;
    int brow = tid >> 4;
    int bcol = (tid & 15) * 4;

    for (int k0 = 0; k0 < K; k0 += BK) {
        float4 av = make_float4(0.f, 0.f, 0.f, 0.f);
        int gr = bm + arow;
        if (gr < M) av = *reinterpret_cast<const float4*>(A + (size_t)gr * K + k0 + akc);
        sA[akc + 0][arow] = av.x;
        sA[akc + 1][arow] = av.y;
        sA[akc + 2][arow] = av.z;
        sA[akc + 3][arow] = av.w;
        float4 bv = *reinterpret_cast<const float4*>(B + (size_t)(k0 + brow) * Ncol + bn + bcol);
        *reinterpret_cast<float4*>(&sB[brow][bcol]) = bv;
        __syncthreads();
#pragma unroll
        for (int k = 0; k < BK; k++) {
            float4 a4 = *reinterpret_cast<const float4*>(&sA[k][ty * 4]);
            float4 b4 = *reinterpret_cast<const float4*>(&sB[k][tx * 4]);
            float a[4] = {a4.x, a4.y, a4.z, a4.w};
            float b[4] = {b4.x, b4.y, b4.z, b4.w};
#pragma unroll
            for (int i = 0; i < 4; i++)
#pragma unroll
                for (int j = 0; j < 4; j++) acc[i][j] = fmaf(a[i], b[j], acc[i][j]);
        }
        __syncthreads();
    }
#pragma unroll
    for (int i = 0; i < 4; i++) {
        int r = bm + ty * 4 + i;
        if (r >= M) break;
#pragma unroll
        for (int j = 0; j < 4; j++) {
            int c = bn + tx * 4 + j;
            float v = acc[i][j];
            if (bias) v += bias[c];
            if (act) v = eluf(v);
            C[(size_t)r * Ncol + c] = v;
        }
    }
}

// ---------------- 128x128 SGEMM with f32x2 packed FMA ----------------
#define GBM 128
#define GBN 128
#define GBK 16
#define GAPAD 144

__global__ __launch_bounds__(256) void gemm128_kernel(
    const float* __restrict__ A, const float* __restrict__ B,
    float* __restrict__ C, int M, int Ncol, int K) {
    __shared__ float sA[GBK][GAPAD];
    __shared__ float sB[GBK][GBN];
    int tid = threadIdx.x;  // 256
    int bm = blockIdx.x * GBM, bn = blockIdx.y * GBN;
    int ty = tid >> 4, tx = tid & 15;

    int lrow = tid >> 1;
    int lkc  = (tid & 1) * 8;
    int lkb  = tid >> 4;
    int lcol = (tid & 15) * 8;

    unsigned long long acc[8][4];
#pragma unroll
    for (int i = 0; i < 8; i++)
#pragma unroll
        for (int j = 0; j < 4; j++) acc[i][j] = 0ull;

    for (int k0 = 0; k0 < K; k0 += GBK) {
        float4 av0 = make_float4(0.f, 0.f, 0.f, 0.f);
        float4 av1 = make_float4(0.f, 0.f, 0.f, 0.f);
        int gr = bm + lrow;
        if (gr < M) {
            av0 = *reinterpret_cast<const float4*>(A + (size_t)gr * K + k0 + lkc);
            av1 = *reinterpret_cast<const float4*>(A + (size_t)gr * K + k0 + lkc + 4);
        }
        sA[lkc + 0][lrow] = av0.x;
        sA[lkc + 1][lrow] = av0.y;
        sA[lkc + 2][lrow] = av0.z;
        sA[lkc + 3][lrow] = av0.w;
        sA[lkc + 4][lrow] = av1.x;
        sA[lkc + 5][lrow] = av1.y;
        sA[lkc + 6][lrow] = av1.z;
        sA[lkc + 7][lrow] = av1.w;
        float4 bv0 = *reinterpret_cast<const float4*>(B + (size_t)(k0 + lkb) * Ncol + bn + lcol);
        float4 bv1 = *reinterpret_cast<const float4*>(B + (size_t)(k0 + lkb) * Ncol + bn + lcol + 4);
        *reinterpret_cast<float4*>(&sB[lkb][lcol]) = bv0;
        *reinterpret_cast<float4*>(&sB[lkb][lcol + 4]) = bv1;
        __syncthreads();
#pragma unroll
        for (int k = 0; k < GBK; k++) {
            float4 a0 = *reinterpret_cast<const float4*>(&sA[k][ty * 4]);
            float4 a1 = *reinterpret_cast<const float4*>(&sA[k][64 + ty * 4]);
            float4 b0 = *reinterpret_cast<const float4*>(&sB[k][tx * 4]);
            float4 b1 = *reinterpret_cast<const float4*>(&sB[k][64 + tx * 4]);
            unsigned long long bp[4];
            bp[0] = packf(b0.x, b0.y);
            bp[1] = packf(b0.z, b0.w);
            bp[2] = packf(b1.x, b1.y);
            bp[3] = packf(b1.z, b1.w);
            float a[8] = {a0.x, a0.y, a0.z, a0.w, a1.x, a1.y, a1.z, a1.w};
#pragma unroll
            for (int i = 0; i < 8; i++) {
                unsigned long long ad = dupf(a[i]);
#pragma unroll
                for (int jp = 0; jp < 4; jp++) fma2(acc[i][jp], ad, bp[jp]);
            }
        }
        __syncthreads();
    }

#pragma unroll
    for (int i = 0; i < 8; i++) {
        int r = bm + ((i < 4) ? (ty * 4 + i) : (64 + ty * 4 + i - 4));
        if (r >= M) continue;
        float v[8];
#pragma unroll
        for (int jp = 0; jp < 4; jp++) unpackf(acc[i][jp], v[jp * 2], v[jp * 2 + 1]);
        float* crow = C + (size_t)r * Ncol + bn;
        *reinterpret_cast<float4*>(crow + tx * 4) = make_float4(v[0], v[1], v[2], v[3]);
        *reinterpret_cast<float4*>(crow + 64 + tx * 4) = make_float4(v[4], v[5], v[6], v[7]);
    }
}

// ---------------- attention scores ----------------
__global__ void att_scores_kernel(const float* __restrict__ feat,
                                  const float* __restrict__ att_src,
                                  const float* __restrict__ att_dst) {
    int n = blockIdx.x;
    int t = threadIdx.x;  // 128
    int h = t >> 5, lane = t & 31;
    const float* f = feat + (size_t)n * HCC + h * HIDC;
    float s1 = f[lane] * att_src[h * HIDC + lane] + f[lane + 32] * att_src[h * HIDC + lane + 32];
    float s2 = f[lane] * att_dst[h * HIDC + lane] + f[lane + 32] * att_dst[h * HIDC + lane + 32];
#pragma unroll
    for (int o = 16; o; o >>= 1) {
        s1 += __shfl_xor_sync(0xffffffffu, s1, o);
        s2 += __shfl_xor_sync(0xffffffffu, s2, o);
    }
    if (lane == 0) {
        g_asrc[n * HEADSC + h] = s1;
        g_adst[n * HEADSC + h] = s2;
    }
}

// ---------------- single-pass warp-per-dst GAT aggregation ----------------
// alpha = exp(e)/sum(exp(e))  (no max shift needed: |e| is small; exact algebra)
// accumulate unnormalized sum + denominator in one pass over edges.
#define AGG_WARPS 8
__global__ __launch_bounds__(AGG_WARPS * 32) void gat_fused_kernel(
    const float* __restrict__ feat, const float* __restrict__ bias,
    float* __restrict__ out) {
    __shared__ float s_p[AGG_WARPS][32][HEADSC];
    __shared__ int s_src[AGG_WARPS][32];

    int wid = threadIdx.x >> 5;
    int lane = threadIdx.x & 31;
    int d = blockIdx.x * AGG_WARPS + wid;
    if (d >= NN) return;

    int base = g_off[d];
    int deg = g_off[d + 1] - base;
    int total = deg + 1;  // + self-loop

    float4 ad4 = *reinterpret_cast<const float4*>(g_adst + (size_t)d * HEADSC);
    float adst[4] = {ad4.x, ad4.y, ad4.z, ad4.w};

    int myc = lane * 8;        // channel base for this lane
    int myh = lane >> 3;       // head = myc / 64
    float acc[8] = {0.f, 0.f, 0.f, 0.f, 0.f, 0.f, 0.f, 0.f};
    float den = 0.f;           // per-lane partial of sum over ALL heads? no: per-head

    // per-lane denominator partials for all 4 heads
    float denh[4] = {0.f, 0.f, 0.f, 0.f};

    for (int ch = 0; ch < total; ch += 32) {
        int j = ch + lane;
        if (j < total) {
            int s = (j < deg) ? g_srclist[base + j] : d;
            float4 as4 = *reinterpret_cast<const float4*>(g_asrc + (size_t)s * HEADSC);
            float p0 = __expf(lrelu(as4.x + adst[0]));
            float p1 = __expf(lrelu(as4.y + adst[1]));
            float p2 = __expf(lrelu(as4.z + adst[2]));
            float p3 = __expf(lrelu(as4.w + adst[3]));
            denh[0] += p0; denh[1] += p1; denh[2] += p2; denh[3] += p3;
            s_p[wid][lane][0] = p0;
            s_p[wid][lane][1] = p1;
            s_p[wid][lane][2] = p2;
            s_p[wid][lane][3] = p3;
            s_src[wid][lane] = s;
        }
        __syncwarp();
        int lim = min(32, total - ch);
        int jj = 0;
        for (; jj + 2 <= lim; jj += 2) {
            int s0 = s_src[wid][jj];
            int s1 = s_src[wid][jj + 1];
            float a0 = s_p[wid][jj][myh];
            float a1 = s_p[wid][jj + 1][myh];
            float4 f00 = *reinterpret_cast<const float4*>(feat + (size_t)s0 * HCC + myc);
            float4 f01 = *reinterpret_cast<const float4*>(feat + (size_t)s0 * HCC + myc + 4);
            float4 f10 = *reinterpret_cast<const float4*>(feat + (size_t)s1 * HCC + myc);
            float4 f11 = *reinterpret_cast<const float4*>(feat + (size_t)s1 * HCC + myc + 4);
            acc[0] = fmaf(a0, f00.x, acc[0]); acc[1] = fmaf(a0, f00.y, acc[1]);
            acc[2] = fmaf(a0, f00.z, acc[2]); acc[3] = fmaf(a0, f00.w, acc[3]);
            acc[4] = fmaf(a0, f01.x, acc[4]); acc[5] = fmaf(a0, f01.y, acc[5]);
            acc[6] = fmaf(a0, f01.z, acc[6]); acc[7] = fmaf(a0, f01.w, acc[7]);
            acc[0] = fmaf(a1, f10.x, acc[0]); acc[1] = fmaf(a1, f10.y, acc[1]);
            acc[2] = fmaf(a1, f10.z, acc[2]); acc[3] = fmaf(a1, f10.w, acc[3]);
            acc[4] = fmaf(a1, f11.x, acc[4]); acc[5] = fmaf(a1, f11.y, acc[5]);
            acc[6] = fmaf(a1, f11.z, acc[6]); acc[7] = fmaf(a1, f11.w, acc[7]);
        }
        for (; jj < lim; jj++) {
            int s0 = s_src[wid][jj];
            float a0 = s_p[wid][jj][myh];
            float4 f00 = *reinterpret_cast<const float4*>(feat + (size_t)s0 * HCC + myc);
            float4 f01 = *reinterpret_cast<const float4*>(feat + (size_t)s0 * HCC + myc + 4);
            acc[0] = fmaf(a0, f00.x, acc[0]); acc[1] = fmaf(a0, f00.y, acc[1]);
            acc[2] = fmaf(a0, f00.z, acc[2]); acc[3] = fmaf(a0, f00.w, acc[3]);
            acc[4] = fmaf(a0, f01.x, acc[4]); acc[5] = fmaf(a0, f01.y, acc[5]);
            acc[6] = fmaf(a0, f01.z, acc[6]); acc[7] = fmaf(a0, f01.w, acc[7]);
        }
        __syncwarp();
    }

    // reduce per-head denominators across the warp
#pragma unroll
    for (int o = 16; o; o >>= 1) {
#pragma unroll
        for (int h = 0; h < 4; h++) denh[h] += __shfl_xor_sync(0xffffffffu, denh[h], o);
    }
    float inv = 1.f / (denh[myh] + 1e-16f);

    float* orow = out + (size_t)d * HCC + myc;
    const float* brow = bias + myc;
    float4 b0 = *reinterpret_cast<const float4*>(brow);
    float4 b1 = *reinterpret_cast<const float4*>(brow + 4);
    float4 r0 = make_float4(eluf(acc[0] * inv + b0.x), eluf(acc[1] * inv + b0.y),
                            eluf(acc[2] * inv + b0.z), eluf(acc[3] * inv + b0.w));
    float4 r1 = make_float4(eluf(acc[4] * inv + b1.x), eluf(acc[5] * inv + b1.y),
                            eluf(acc[6] * inv + b1.z), eluf(acc[7] * inv + b1.w));
    *reinterpret_cast<float4*>(orow) = r0;
    *reinterpret_cast<float4*>(orow + 4) = r1;
}

// ---------------- fused out projection + layernorm (32 nodes / block, f32x2) ----------------
#define ONB 32
__global__ __launch_bounds__(256) void onl_kernel(
    const float* __restrict__ hin, const float* __restrict__ Wout,
    const float* __restrict__ bout, const float* __restrict__ gamma,
    const float* __restrict__ beta, float* __restrict__ out) {
    __shared__ float sA[32][ONB + 1];
    __shared__ float sB[32][OUT_DIMC];
    int tid = threadIdx.x;  // 256
    int bm = blockIdx.x * ONB;
    int ty = tid >> 5;
    int tx = tid & 31;

    int lrow = tid >> 3;
    int lkc  = (tid & 7) * 4;
    int lkb  = tid >> 3;
    int lc16 = (tid & 7) * 16;

    unsigned long long acc[4][2];
#pragma unroll
    for (int i = 0; i < 4; i++) { acc[i][0] = 0ull; acc[i][1] = 0ull; }

    for (int k0 = 0; k0 < HCC; k0 += 32) {
        float4 av = make_float4(0.f, 0.f, 0.f, 0.f);
        int gr = bm + lrow;
        if (gr < NN) av = *reinterpret_cast<const float4*>(hin + (size_t)gr * HCC + k0 + lkc);
        sA[lkc + 0][lrow] = av.x;
        sA[lkc + 1][lrow] = av.y;
        sA[lkc + 2][lrow] = av.z;
        sA[lkc + 3][lrow] = av.w;
#pragma unroll
        for (int q = 0; q < 4; q++) {
            float4 bv = *reinterpret_cast<const float4*>(Wout + (size_t)(k0 + lkb) * OUT_DIMC + lc16 + q * 4);
            *reinterpret_cast<float4*>(&sB[lkb][lc16 + q * 4]) = bv;
        }
        __syncthreads();
#pragma unroll 8
        for (int k = 0; k < 32; k++) {
            float4 b4 = *reinterpret_cast<const float4*>(&sB[k][tx * 4]);
            unsigned long long bp0 = packf(b4.x, b4.y);
            unsigned long long bp1 = packf(b4.z, b4.w);
#pragma unroll
            for (int i = 0; i < 4; i++) {
                unsigned long long ad = dupf(sA[k][ty * 4 + i]);
                fma2(acc[i][0], ad, bp0);
                fma2(acc[i][1], ad, bp1);
            }
        }
        __syncthreads();
    }

    float b0 = bout[tx * 4 + 0], b1 = bout[tx * 4 + 1], b2 = bout[tx * 4 + 2], b3 = bout[tx * 4 + 3];
    float g0 = gamma[tx * 4 + 0], g1 = gamma[tx * 4 + 1], g2 = gamma[tx * 4 + 2], g3 = gamma[tx * 4 + 3];
    float be0 = beta[tx * 4 + 0], be1 = beta[tx * 4 + 1], be2 = beta[tx * 4 + 2], be3 = beta[tx * 4 + 3];
#pragma unroll
    for (int i = 0; i < 4; i++) {
        int r = bm + ty * 4 + i;
        float v[4];
        unpackf(acc[i][0], v[0], v[1]);
        unpackf(acc[i][1], v[2], v[3]);
        v[0] += b0; v[1] += b1; v[2] += b2; v[3] += b3;
        float psum = v[0] + v[1] + v[2] + v[3];
#pragma unroll
        for (int o = 16; o; o >>= 1) psum += __shfl_xor_sync(0xffffffffu, psum, o);
        float mu = psum * (1.f / OUT_DIMC);
        float d0 = v[0] - mu, d1 = v[1] - mu, d2 = v[2] - mu, d3 = v[3] - mu;
        float pss = d0 * d0 + d1 * d1 + d2 * d2 + d3 * d3;
#pragma unroll
        for (int o = 16; o; o >>= 1) pss += __shfl_xor_sync(0xffffffffu, pss, o);
        float inv = rsqrtf(pss * (1.f / OUT_DIMC) + LN_EPSF);
        if (r < NN) {
            float4 res = make_float4(d0 * inv * g0 + be0, d1 * inv * g1 + be1,
                                     d2 * inv * g2 + be2, d3 * inv * g3 + be3);
            *reinterpret_cast<float4*>(out + (size_t)r * OUT_DIMC + tx * 4) = res;
        }
    }
}

// ---------------- launch ----------------
extern "C" void kernel_launch(void* const* d_in, const int* in_sizes, int n_in,
                              void* d_out, int out_size) {
    const float* x     = (const float*)d_in[0];
    const int*   ei    = (const int*)d_in[1];
    const float* W_in  = (const float*)d_in[2];
    const float* b_in  = (const float*)d_in[3];
    const float* lin0  = (const float*)d_in[4];
    const float* att0s = (const float*)d_in[5];
    const float* att0d = (const float*)d_in[6];
    const float* bias0 = (const float*)d_in[7];
    const float* lin1  = (const float*)d_in[8];
    const float* att1s = (const float*)d_in[9];
    const float* att1d = (const float*)d_in[10];
    const float* bias1 = (const float*)d_in[11];
    const float* Wout  = (const float*)d_in[12];
    const float* bout  = (const float*)d_in[13];
    const float* gamma = (const float*)d_in[14];
    const float* beta  = (const float*)d_in[15];
    float* out = (float*)d_out;

    int E = in_sizes[1] / 2;
    if (E > EE) E = EE;
    const int* srcp = ei;
    const int* dstp = ei + E;

    float *h0p = nullptr, *featp = nullptr, *aggp = nullptr;
    cudaGetSymbolAddress((void**)&h0p, g_h0);
    cudaGetSymbolAddress((void**)&featp, g_feat);
    cudaGetSymbolAddress((void**)&aggp, g_agg);

    // graph build (CSR of incoming edges per dst)
    zero_deg_kernel<<<(NN + 255) / 256, 256>>>();
    count_deg_kernel<<<(E + 255) / 256, 256>>>(dstp, E);
    scan_deg_kernel<<<1, 1024>>>();
    scatter_kernel<<<(E + 255) / 256, 256>>>(srcp, dstp, E);

    // input projection + ELU
    gemm_kernel<<<dim3((NN + BM - 1) / BM, HIDC / BN), 256>>>(x, W_in, b_in, h0p, NN, HIDC, IN_DIMC, 1);

    const int gx128 = (NN + GBM - 1) / GBM;
    const int gagg = (NN + AGG_WARPS - 1) / AGG_WARPS;

    // GAT layer 0
    gemm128_kernel<<<dim3(gx128, HCC / GBN), 256>>>(h0p, lin0, featp, NN, HCC, HIDC);
    att_scores_kernel<<<NN, 128>>>(featp, att0s, att0d);
    gat_fused_kernel<<<gagg, AGG_WARPS * 32>>>(featp, bias0, aggp);

    // GAT layer 1
    gemm128_kernel<<<dim3(gx128, HCC / GBN), 256>>>(aggp, lin1, featp, NN, HCC, HCC);
    att_scores_kernel<<<NN, 128>>>(featp, att1s, att1d);
    gat_fused_kernel<<<gagg, AGG_WARPS * 32>>>(featp, bias1, aggp);

    // output projection + layernorm
    onl_kernel<<<(NN + ONB - 1) / ONB, 256>>>(aggp, Wout, bout, gamma, beta, out);
}

// round 4
// speedup vs baseline: 2.1094x; 1.1889x over previous
#include <cuda_runtime.h>
#include <math.h>

#define NN 50000
#define EE 800000
#define IN_DIMC 32
#define HIDC 64
#define HEADSC 4
#define HCC 256
#define OUT_DIMC 128
#define LN_EPSF 1e-5f
#define NEG_SLOPEF 0.2f

// ---------------- scratch (device globals; no allocation allowed) ----------------
__device__ float g_h0[NN * HIDC];
__device__ float g_feat[NN * HCC];
__device__ float g_agg[NN * HCC];
__device__ float g_asrc[NN * HEADSC];
__device__ float g_adst[NN * HEADSC];
__device__ int   g_deg[NN];
__device__ int   g_off[NN + 1];
__device__ int   g_cur[NN];
__device__ int   g_srclist[EE];
__device__ int   g_bsum[256];

__device__ __forceinline__ float eluf(float x) { return x > 0.f ? x : expm1f(x); }
__device__ __forceinline__ float lrelu(float x) { return x > 0.f ? x : NEG_SLOPEF * x; }

// packed fp32x2 helpers (sm_100+ FFMA2)
__device__ __forceinline__ void fma2(unsigned long long& d, unsigned long long a, unsigned long long b) {
    asm("fma.rn.f32x2 %0, %1, %2, %0;" : "+l"(d) : "l"(a), "l"(b));
}
__device__ __forceinline__ unsigned long long dupf(float a) {
    unsigned long long r;
    asm("mov.b64 %0, {%1, %1};" : "=l"(r) : "f"(a));
    return r;
}
__device__ __forceinline__ unsigned long long packf(float a, float b) {
    unsigned long long r;
    asm("mov.b64 %0, {%1, %2};" : "=l"(r) : "f"(a), "f"(b));
    return r;
}
__device__ __forceinline__ void unpackf(unsigned long long v, float& lo, float& hi) {
    asm("mov.b64 {%0, %1}, %2;" : "=f"(lo), "=f"(hi) : "l"(v));
}

// ---------------- graph build ----------------
__global__ void zero_deg_kernel() {
    int i = blockIdx.x * blockDim.x + threadIdx.x;
    if (i < NN) g_deg[i] = 0;
}

__global__ void count_deg_kernel(const int* __restrict__ dst, int E) {
    int i = blockIdx.x * blockDim.x + threadIdx.x;
    if (i < E) atomicAdd(&g_deg[dst[i]], 1);
}

// 3-phase multi-block exclusive scan of g_deg -> g_off
__global__ void scan_p1_kernel() {
    __shared__ int s[256];
    int t = threadIdx.x;
    int i = blockIdx.x * 256 + t;
    int v = (i < NN) ? g_deg[i] : 0;
    s[t] = v;
    __syncthreads();
#pragma unroll
    for (int d = 1; d < 256; d <<= 1) {
        int u = (t >= d) ? s[t - d] : 0;
        __syncthreads();
        s[t] += u;
        __syncthreads();
    }
    if (i < NN) g_off[i] = s[t] - v;  // exclusive within block
    if (t == 255) g_bsum[blockIdx.x] = s[255];
}

__global__ void scan_p2_kernel(int nblocks) {
    __shared__ int s[256];
    int t = threadIdx.x;
    int v = (t < nblocks) ? g_bsum[t] : 0;
    s[t] = v;
    __syncthreads();
#pragma unroll
    for (int d = 1; d < 256; d <<= 1) {
        int u = (t >= d) ? s[t - d] : 0;
        __syncthreads();
        s[t] += u;
        __syncthreads();
    }
    if (t < nblocks) g_bsum[t] = s[t] - v;  // exclusive block bases
}

__global__ void scan_p3_kernel() {
    int i = blockIdx.x * 256 + threadIdx.x;
    if (i < NN) {
        int o = g_off[i] + g_bsum[blockIdx.x];
        g_off[i] = o;
        g_cur[i] = o;
        if (i == NN - 1) g_off[NN] = o + g_deg[i];
    }
}

__global__ void scatter_kernel(const int* __restrict__ src, const int* __restrict__ dst, int E) {
    int i = blockIdx.x * blockDim.x + threadIdx.x;
    if (i < E) {
        int p = atomicAdd(&g_cur[dst[i]], 1);
        g_srclist[p] = src[i];
    }
}

// ---------------- small SGEMM (input projection, N=64) ----------------
#define BM 64
#define BN 64
#define BK 16
__global__ void gemm_kernel(const float* __restrict__ A, const float* __restrict__ B,
                            const float* __restrict__ bias, float* __restrict__ C,
                            int M, int Ncol, int K, int act) {
    __shared__ float sA[BK][BM];
    __shared__ float sB[BK][BN];
    int tid = threadIdx.x;
    int bm = blockIdx.x * BM, bn = blockIdx.y * BN;
    int ty = tid / 16, tx = tid % 16;
    float acc[4][4] = {};
    int arow = tid >> 2;
    int akc  = (tid & 3) * 4;
    int brow = tid >> 4;
    int bcol = (tid & 15) * 4;

    for (int k0 = 0; k0 < K; k0 += BK) {
        float4 av = make_float4(0.f, 0.f, 0.f, 0.f);
        int gr = bm + arow;
        if (gr < M) av = *reinterpret_cast<const float4*>(A + (size_t)gr * K + k0 + akc);
        sA[akc + 0][arow] = av.x;
        sA[akc + 1][arow] = av.y;
        sA[akc + 2][arow] = av.z;
        sA[akc + 3][arow] = av.w;
        float4 bv = *reinterpret_cast<const float4*>(B + (size_t)(k0 + brow) * Ncol + bn + bcol);
        *reinterpret_cast<float4*>(&sB[brow][bcol]) = bv;
        __syncthreads();
#pragma unroll
        for (int k = 0; k < BK; k++) {
            float4 a4 = *reinterpret_cast<const float4*>(&sA[k][ty * 4]);
            float4 b4 = *reinterpret_cast<const float4*>(&sB[k][tx * 4]);
            float a[4] = {a4.x, a4.y, a4.z, a4.w};
            float b[4] = {b4.x, b4.y, b4.z, b4.w};
#pragma unroll
            for (int i = 0; i < 4; i++)
#pragma unroll
                for (int j = 0; j < 4; j++) acc[i][j] = fmaf(a[i], b[j], acc[i][j]);
        }
        __syncthreads();
    }
#pragma unroll
    for (int i = 0; i < 4; i++) {
        int r = bm + ty * 4 + i;
        if (r >= M) break;
#pragma unroll
        for (int j = 0; j < 4; j++) {
            int c = bn + tx * 4 + j;
            float v = acc[i][j];
            if (bias) v += bias[c];
            if (act) v = eluf(v);
            C[(size_t)r * Ncol + c] = v;
        }
    }
}

// ---------------- fused 128x256 SGEMM + attention-score epilogue ----------------
// C = A[M,K] @ B[K,256]; per-row att_src/att_dst dot products computed in epilogue.
// 512 threads; microtile 8 rows x 8 cols; accumulators packed f32x2 along M.
#define TBM 128
#define TBN 256
#define TBK 16
#define TAPAD 132

__global__ __launch_bounds__(512) void gemm256_att_kernel(
    const float* __restrict__ A, const float* __restrict__ B,
    float* __restrict__ C, const float* __restrict__ att_src,
    const float* __restrict__ att_dst, int M, int K) {
    __shared__ float sA[TBK][TAPAD];
    __shared__ float sB[TBK][TBN];
    __shared__ float s_as[HCC];   // att_src [h*64+ch]
    __shared__ float s_ad[HCC];   // att_dst

    int tid = threadIdx.x;        // 512
    int bm = blockIdx.x * TBM;
    int ty = tid >> 5;            // 0..15 -> rows 8*ty .. 8*ty+7
    int tx = tid & 31;            // cols tx*4..+3 and 128+tx*4..+3

    if (tid < HCC) {
        s_as[tid] = att_src[tid];
        s_ad[tid] = att_dst[tid];
    }

    int lrow = tid >> 2;          // 0..127 (A loader)
    int lkc  = (tid & 3) * 4;     // 0..12
    int lkb  = tid >> 5;          // 0..15  (B loader)
    int lcol = (tid & 31) * 8;    // 0..248

    // acc[p][j]: p = M-pair (rows 8ty+2p, 8ty+2p+1), j = col index (0..3 -> tx*4+j, 4..7 -> 128+tx*4+j-4)
    unsigned long long acc[4][8];
#pragma unroll
    for (int p = 0; p < 4; p++)
#pragma unroll
        for (int j = 0; j < 8; j++) acc[p][j] = 0ull;

    for (int k0 = 0; k0 < K; k0 += TBK) {
        float4 av = make_float4(0.f, 0.f, 0.f, 0.f);
        int gr = bm + lrow;
        if (gr < M) av = *reinterpret_cast<const float4*>(A + (size_t)gr * K + k0 + lkc);
        sA[lkc + 0][lrow] = av.x;
        sA[lkc + 1][lrow] = av.y;
        sA[lkc + 2][lrow] = av.z;
        sA[lkc + 3][lrow] = av.w;
        float4 bv0 = *reinterpret_cast<const float4*>(B + (size_t)(k0 + lkb) * TBN + lcol);
        float4 bv1 = *reinterpret_cast<const float4*>(B + (size_t)(k0 + lkb) * TBN + lcol + 4);
        *reinterpret_cast<float4*>(&sB[lkb][lcol]) = bv0;
        *reinterpret_cast<float4*>(&sB[lkb][lcol + 4]) = bv1;
        __syncthreads();
#pragma unroll
        for (int k = 0; k < TBK; k++) {
            // A: broadcast loads (all lanes in warp share ty) -> M-pairs free from register pairs
            float4 a0 = *reinterpret_cast<const float4*>(&sA[k][ty * 8]);
            float4 a1 = *reinterpret_cast<const float4*>(&sA[k][ty * 8 + 4]);
            unsigned long long ap[4];
            ap[0] = packf(a0.x, a0.y);
            ap[1] = packf(a0.z, a0.w);
            ap[2] = packf(a1.x, a1.y);
            ap[3] = packf(a1.z, a1.w);
            float4 b0 = *reinterpret_cast<const float4*>(&sB[k][tx * 4]);
            float4 b1 = *reinterpret_cast<const float4*>(&sB[k][128 + tx * 4]);
            float b[8] = {b0.x, b0.y, b0.z, b0.w, b1.x, b1.y, b1.z, b1.w};
#pragma unroll
            for (int j = 0; j < 8; j++) {
                unsigned long long bd = dupf(b[j]);
#pragma unroll
                for (int p = 0; p < 4; p++) fma2(acc[p][j], ap[p], bd);
            }
        }
        __syncthreads();
    }

    // epilogue: store C rows + per-row attention dot products
    int h_lo = tx >> 4;         // head of cols tx*4..+3   (0 or 1)
    int h_hi = 2 + h_lo;        // head of cols 128+tx*4..+3
    int ch = (tx & 15) * 4;     // channel-within-head base
    float wsl[4], wsh[4], wdl[4], wdh[4];
#pragma unroll
    for (int q = 0; q < 4; q++) {
        wsl[q] = s_as[h_lo * 64 + ch + q];
        wsh[q] = s_as[h_hi * 64 + ch + q];
        wdl[q] = s_ad[h_lo * 64 + ch + q];
        wdh[q] = s_ad[h_hi * 64 + ch + q];
    }

#pragma unroll
    for (int p = 0; p < 4; p++) {
#pragma unroll
        for (int half = 0; half < 2; half++) {
            int r = bm + ty * 8 + 2 * p + half;
            float v[8];
#pragma unroll
            for (int j = 0; j < 8; j++) {
                float lo, hi;
                unpackf(acc[p][j], lo, hi);
                v[j] = half ? hi : lo;
            }
            // att partials: lanes 0-15 own heads {0,2}; lanes 16-31 own heads {1,3}
            float p1l = v[0] * wsl[0] + v[1] * wsl[1] + v[2] * wsl[2] + v[3] * wsl[3];
            float p1h = v[4] * wsh[0] + v[5] * wsh[1] + v[6] * wsh[2] + v[7] * wsh[3];
            float p2l = v[0] * wdl[0] + v[1] * wdl[1] + v[2] * wdl[2] + v[3] * wdl[3];
            float p2h = v[4] * wdh[0] + v[5] * wdh[1] + v[6] * wdh[2] + v[7] * wdh[3];
#pragma unroll
            for (int o = 8; o; o >>= 1) {
                p1l += __shfl_xor_sync(0xffffffffu, p1l, o);
                p1h += __shfl_xor_sync(0xffffffffu, p1h, o);
                p2l += __shfl_xor_sync(0xffffffffu, p2l, o);
                p2h += __shfl_xor_sync(0xffffffffu, p2h, o);
            }
            if (r < M) {
                if ((tx & 15) == 0) {
                    g_asrc[(size_t)r * HEADSC + h_lo] = p1l;
                    g_asrc[(size_t)r * HEADSC + h_hi] = p1h;
                    g_adst[(size_t)r * HEADSC + h_lo] = p2l;
                    g_adst[(size_t)r * HEADSC + h_hi] = p2h;
                }
                float* crow = C + (size_t)r * HCC;
                *reinterpret_cast<float4*>(crow + tx * 4) = make_float4(v[0], v[1], v[2], v[3]);
                *reinterpret_cast<float4*>(crow + 128 + tx * 4) = make_float4(v[4], v[5], v[6], v[7]);
            }
        }
    }
}

// ---------------- single-pass warp-per-dst GAT aggregation ----------------
#define AGG_WARPS 8
__global__ __launch_bounds__(AGG_WARPS * 32) void gat_fused_kernel(
    const float* __restrict__ feat, const float* __restrict__ bias,
    float* __restrict__ out) {
    __shared__ float s_p[AGG_WARPS][32][HEADSC];
    __shared__ int s_src[AGG_WARPS][32];

    int wid = threadIdx.x >> 5;
    int lane = threadIdx.x & 31;
    int d = blockIdx.x * AGG_WARPS + wid;
    if (d >= NN) return;

    int base = g_off[d];
    int deg = g_off[d + 1] - base;
    int total = deg + 1;  // + self-loop

    float4 ad4 = *reinterpret_cast<const float4*>(g_adst + (size_t)d * HEADSC);
    float adst[4] = {ad4.x, ad4.y, ad4.z, ad4.w};

    int myc = lane * 8;
    int myh = lane >> 3;
    float acc[8] = {0.f, 0.f, 0.f, 0.f, 0.f, 0.f, 0.f, 0.f};
    float denh[4] = {0.f, 0.f, 0.f, 0.f};

    for (int ch = 0; ch < total; ch += 32) {
        int j = ch + lane;
        if (j < total) {
            int s = (j < deg) ? g_srclist[base + j] : d;
            float4 as4 = *reinterpret_cast<const float4*>(g_asrc + (size_t)s * HEADSC);
            float p0 = __expf(lrelu(as4.x + adst[0]));
            float p1 = __expf(lrelu(as4.y + adst[1]));
            float p2 = __expf(lrelu(as4.z + adst[2]));
            float p3 = __expf(lrelu(as4.w + adst[3]));
            denh[0] += p0; denh[1] += p1; denh[2] += p2; denh[3] += p3;
            s_p[wid][lane][0] = p0;
            s_p[wid][lane][1] = p1;
            s_p[wid][lane][2] = p2;
            s_p[wid][lane][3] = p3;
            s_src[wid][lane] = s;
        }
        __syncwarp();
        int lim = min(32, total - ch);
        int jj = 0;
        for (; jj + 2 <= lim; jj += 2) {
            int s0 = s_src[wid][jj];
            int s1 = s_src[wid][jj + 1];
            float a0 = s_p[wid][jj][myh];
            float a1 = s_p[wid][jj + 1][myh];
            float4 f00 = *reinterpret_cast<const float4*>(feat + (size_t)s0 * HCC + myc);
            float4 f01 = *reinterpret_cast<const float4*>(feat + (size_t)s0 * HCC + myc + 4);
            float4 f10 = *reinterpret_cast<const float4*>(feat + (size_t)s1 * HCC + myc);
            float4 f11 = *reinterpret_cast<const float4*>(feat + (size_t)s1 * HCC + myc + 4);
            acc[0] = fmaf(a0, f00.x, acc[0]); acc[1] = fmaf(a0, f00.y, acc[1]);
            acc[2] = fmaf(a0, f00.z, acc[2]); acc[3] = fmaf(a0, f00.w, acc[3]);
            acc[4] = fmaf(a0, f01.x, acc[4]); acc[5] = fmaf(a0, f01.y, acc[5]);
            acc[6] = fmaf(a0, f01.z, acc[6]); acc[7] = fmaf(a0, f01.w, acc[7]);
            acc[0] = fmaf(a1, f10.x, acc[0]); acc[1] = fmaf(a1, f10.y, acc[1]);
            acc[2] = fmaf(a1, f10.z, acc[2]); acc[3] = fmaf(a1, f10.w, acc[3]);
            acc[4] = fmaf(a1, f11.x, acc[4]); acc[5] = fmaf(a1, f11.y, acc[5]);
            acc[6] = fmaf(a1, f11.z, acc[6]); acc[7] = fmaf(a1, f11.w, acc[7]);
        }
        for (; jj < lim; jj++) {
            int s0 = s_src[wid][jj];
            float a0 = s_p[wid][jj][myh];
            float4 f00 = *reinterpret_cast<const float4*>(feat + (size_t)s0 * HCC + myc);
            float4 f01 = *reinterpret_cast<const float4*>(feat + (size_t)s0 * HCC + myc + 4);
            acc[0] = fmaf(a0, f00.x, acc[0]); acc[1] = fmaf(a0, f00.y, acc[1]);
            acc[2] = fmaf(a0, f00.z, acc[2]); acc[3] = fmaf(a0, f00.w, acc[3]);
            acc[4] = fmaf(a0, f01.x, acc[4]); acc[5] = fmaf(a0, f01.y, acc[5]);
            acc[6] = fmaf(a0, f01.z, acc[6]); acc[7] = fmaf(a0, f01.w, acc[7]);
        }
        __syncwarp();
    }

#pragma unroll
    for (int o = 16; o; o >>= 1) {
#pragma unroll
        for (int h = 0; h < 4; h++) denh[h] += __shfl_xor_sync(0xffffffffu, denh[h], o);
    }
    float inv = 1.f / (denh[myh] + 1e-16f);

    float* orow = out + (size_t)d * HCC + myc;
    const float* brow = bias + myc;
    float4 b0 = *reinterpret_cast<const float4*>(brow);
    float4 b1 = *reinterpret_cast<const float4*>(brow + 4);
    float4 r0 = make_float4(eluf(acc[0] * inv + b0.x), eluf(acc[1] * inv + b0.y),
                            eluf(acc[2] * inv + b0.z), eluf(acc[3] * inv + b0.w));
    float4 r1 = make_float4(eluf(acc[4] * inv + b1.x), eluf(acc[5] * inv + b1.y),
                            eluf(acc[6] * inv + b1.z), eluf(acc[7] * inv + b1.w));
    *reinterpret_cast<float4*>(orow) = r0;
    *reinterpret_cast<float4*>(orow + 4) = r1;
}

// ---------------- fused out projection + layernorm (32 nodes / block, f32x2) ----------------
#define ONB 32
__global__ __launch_bounds__(256) void onl_kernel(
    const float* __restrict__ hin, const float* __restrict__ Wout,
    const float* __restrict__ bout, const float* __restrict__ gamma,
    const float* __restrict__ beta, float* __restrict__ out) {
    __shared__ float sA[32][ONB + 1];
    __shared__ float sB[32][OUT_DIMC];
    int tid = threadIdx.x;  // 256
    int bm = blockIdx.x * ONB;
    int ty = tid >> 5;
    int tx = tid & 31;

    int lrow = tid >> 3;
    int lkc  = (tid & 7) * 4;
    int lkb  = tid >> 3;
    int lc16 = (tid & 7) * 16;

    unsigned long long acc[4][2];
#pragma unroll
    for (int i = 0; i < 4; i++) { acc[i][0] = 0ull; acc[i][1] = 0ull; }

    for (int k0 = 0; k0 < HCC; k0 += 32) {
        float4 av = make_float4(0.f, 0.f, 0.f, 0.f);
        int gr = bm + lrow;
        if (gr < NN) av = *reinterpret_cast<const float4*>(hin + (size_t)gr * HCC + k0 + lkc);
        sA[lkc + 0][lrow] = av.x;
        sA[lkc + 1][lrow] = av.y;
        sA[lkc + 2][lrow] = av.z;
        sA[lkc + 3][lrow] = av.w;
#pragma unroll
        for (int q = 0; q < 4; q++) {
            float4 bv = *reinterpret_cast<const float4*>(Wout + (size_t)(k0 + lkb) * OUT_DIMC + lc16 + q * 4);
            *reinterpret_cast<float4*>(&sB[lkb][lc16 + q * 4]) = bv;
        }
        __syncthreads();
#pragma unroll 8
        for (int k = 0; k < 32; k++) {
            float4 b4 = *reinterpret_cast<const float4*>(&sB[k][tx * 4]);
            unsigned long long bp0 = packf(b4.x, b4.y);
            unsigned long long bp1 = packf(b4.z, b4.w);
#pragma unroll
            for (int i = 0; i < 4; i++) {
                unsigned long long ad = dupf(sA[k][ty * 4 + i]);
                fma2(acc[i][0], ad, bp0);
                fma2(acc[i][1], ad, bp1);
            }
        }
        __syncthreads();
    }

    float b0 = bout[tx * 4 + 0], b1 = bout[tx * 4 + 1], b2 = bout[tx * 4 + 2], b3 = bout[tx * 4 + 3];
    float g0 = gamma[tx * 4 + 0], g1 = gamma[tx * 4 + 1], g2 = gamma[tx * 4 + 2], g3 = gamma[tx * 4 + 3];
    float be0 = beta[tx * 4 + 0], be1 = beta[tx * 4 + 1], be2 = beta[tx * 4 + 2], be3 = beta[tx * 4 + 3];
#pragma unroll
    for (int i = 0; i < 4; i++) {
        int r = bm + ty * 4 + i;
        float v[4];
        unpackf(acc[i][0], v[0], v[1]);
        unpackf(acc[i][1], v[2], v[3]);
        v[0] += b0; v[1] += b1; v[2] += b2; v[3] += b3;
        float psum = v[0] + v[1] + v[2] + v[3];
#pragma unroll
        for (int o = 16; o; o >>= 1) psum += __shfl_xor_sync(0xffffffffu, psum, o);
        float mu = psum * (1.f / OUT_DIMC);
        float d0 = v[0] - mu, d1 = v[1] - mu, d2 = v[2] - mu, d3 = v[3] - mu;
        float pss = d0 * d0 + d1 * d1 + d2 * d2 + d3 * d3;
#pragma unroll
        for (int o = 16; o; o >>= 1) pss += __shfl_xor_sync(0xffffffffu, pss, o);
        float inv = rsqrtf(pss * (1.f / OUT_DIMC) + LN_EPSF);
        if (r < NN) {
            float4 res = make_float4(d0 * inv * g0 + be0, d1 * inv * g1 + be1,
                                     d2 * inv * g2 + be2, d3 * inv * g3 + be3);
            *reinterpret_cast<float4*>(out + (size_t)r * OUT_DIMC + tx * 4) = res;
        }
    }
}

// ---------------- launch ----------------
extern "C" void kernel_launch(void* const* d_in, const int* in_sizes, int n_in,
                              void* d_out, int out_size) {
    const float* x     = (const float*)d_in[0];
    const int*   ei    = (const int*)d_in[1];
    const float* W_in  = (const float*)d_in[2];
    const float* b_in  = (const float*)d_in[3];
    const float* lin0  = (const float*)d_in[4];
    const float* att0s = (const float*)d_in[5];
    const float* att0d = (const float*)d_in[6];
    const float* bias0 = (const float*)d_in[7];
    const float* lin1  = (const float*)d_in[8];
    const float* att1s = (const float*)d_in[9];
    const float* att1d = (const float*)d_in[10];
    const float* bias1 = (const float*)d_in[11];
    const float* Wout  = (const float*)d_in[12];
    const float* bout  = (const float*)d_in[13];
    const float* gamma = (const float*)d_in[14];
    const float* beta  = (const float*)d_in[15];
    float* out = (float*)d_out;

    int E = in_sizes[1] / 2;
    if (E > EE) E = EE;
    const int* srcp = ei;
    const int* dstp = ei + E;

    float *h0p = nullptr, *featp = nullptr, *aggp = nullptr;
    cudaGetSymbolAddress((void**)&h0p, g_h0);
    cudaGetSymbolAddress((void**)&featp, g_feat);
    cudaGetSymbolAddress((void**)&aggp, g_agg);

    const int nsb = (NN + 255) / 256;  // scan blocks (196 <= 256)
    const int gx256 = (NN + TBM - 1) / TBM;
    const int gagg = (NN + AGG_WARPS - 1) / AGG_WARPS;

    // launches 0-4 (indices chosen so ncu -s 5 profiles gemm256_att L0)
    zero_deg_kernel<<<nsb, 256>>>();                                   // 0
    count_deg_kernel<<<(E + 255) / 256, 256>>>(dstp, E);               // 1
    scan_p1_kernel<<<nsb, 256>>>();                                    // 2
    scan_p2_kernel<<<1, 256>>>(nsb);                                   // 3
    gemm_kernel<<<dim3((NN + BM - 1) / BM, HIDC / BN), 256>>>(         // 4: input proj + ELU
        x, W_in, b_in, h0p, NN, HIDC, IN_DIMC, 1);

    // 5: GAT layer-0 linear + att scores (profiled by ncu)
    gemm256_att_kernel<<<gx256, 512>>>(h0p, lin0, featp, att0s, att0d, NN, HIDC);

    scan_p3_kernel<<<nsb, 256>>>();                                    // 6
    scatter_kernel<<<(E + 255) / 256, 256>>>(srcp, dstp, E);           // 7

    gat_fused_kernel<<<gagg, AGG_WARPS * 32>>>(featp, bias0, aggp);    // 8

    // GAT layer 1
    gemm256_att_kernel<<<gx256, 512>>>(aggp, lin1, featp, att1s, att1d, NN, HCC);
    gat_fused_kernel<<<gagg, AGG_WARPS * 32>>>(featp, bias1, aggp);

    // output projection + layernorm
    onl_kernel<<<(NN + ONB - 1) / ONB, 256>>>(aggp, Wout, bout, gamma, beta, out);
}